// round 15
// baseline (speedup 1.0000x reference)
#include <cuda_runtime.h>
#include <cuda_fp16.h>
#include <cuda_bf16.h>
#include <cstdint>

// ---------------------------------------------------------------------------
// FeaturePropagation, factorized + warp-MMA fp16 single-term, 3-stage pipeline
//   knn:  3-NN idx+weights (4 threads/point)
//   Y2  = feat2 @ W0[0:256]                          (fp16, 8MB, L2-resident)
//   x1  = BN(relu(feat1 @ W0[256:384] + gather(Y2) + b0))  -> fp16 plane
//   out = BN(relu(x1 @ W1 + b1))                     (fp32)
// ---------------------------------------------------------------------------

#define B_   16
#define N1_  4096
#define N2_  1024
#define C1_  128
#define C2_  256
#define CH_  256
#define M_   (B_ * N1_)
#define M2_  (B_ * N2_)
#define BN_EPS 1e-3f

// ------------------------------- scratch ----------------------------------
__device__ __align__(16) __half g_y2[(size_t)M2_ * CH_];     // 8 MB
__device__ __align__(16) __half g_x1[(size_t)M_ * CH_];
__device__ __align__(16) __half g_f1[(size_t)M_ * C1_];
__device__ __align__(16) __half g_f2[(size_t)M2_ * C2_];
__device__ __align__(16) __half g_w0t[256 * 384];            // W0^T fp16
__device__ __align__(16) __half g_w1t[256 * 256];            // W1^T fp16
__device__ int   g_knn_idx[(size_t)M_ * 3];
__device__ float g_knn_w[(size_t)M_ * 3];

// ------------------------------ helpers -----------------------------------
__device__ __forceinline__ uint32_t smem_u32(const void* p) {
    uint32_t a;
    asm("{ .reg .u64 t; cvta.to.shared.u64 t, %1; cvt.u32.u64 %0, t; }"
        : "=r"(a) : "l"(p));
    return a;
}
__device__ __forceinline__ void cp16(uint32_t dst, const void* src) {
    asm volatile("cp.async.cg.shared.global [%0], [%1], 16;"
                 :: "r"(dst), "l"(src) : "memory");
}
__device__ __forceinline__ void cp_commit() {
    asm volatile("cp.async.commit_group;" ::: "memory");
}
__device__ __forceinline__ void ldsm4(uint32_t& r0, uint32_t& r1, uint32_t& r2,
                                      uint32_t& r3, uint32_t addr) {
    asm volatile("ldmatrix.sync.aligned.m8n8.x4.shared.b16 {%0,%1,%2,%3}, [%4];"
                 : "=r"(r0), "=r"(r1), "=r"(r2), "=r"(r3) : "r"(addr));
}
__device__ __forceinline__ void mma16816(float* c, const uint32_t* a,
                                         uint32_t b0, uint32_t b1) {
    asm volatile(
        "mma.sync.aligned.m16n8k16.row.col.f32.f16.f16.f32 "
        "{%0,%1,%2,%3}, {%4,%5,%6,%7}, {%8,%9}, {%0,%1,%2,%3};"
        : "+f"(c[0]), "+f"(c[1]), "+f"(c[2]), "+f"(c[3])
        : "r"(a[0]), "r"(a[1]), "r"(a[2]), "r"(a[3]), "r"(b0), "r"(b1));
}
__device__ __forceinline__ uint32_t swz(uint32_t off) {
    return off ^ ((off >> 3) & 0x70);
}
__device__ __forceinline__ uint32_t h2_bits(float lo, float hi) {
    __half2 v = __floats2half2_rn(lo, hi);
    return reinterpret_cast<uint32_t&>(v);
}

// ---------------------------------------------------------------------------
// Kernel 1: 3-NN search, 4 threads per point (2 shfl merge rounds).
// grid (N1/32, B), block 128.
// ---------------------------------------------------------------------------
__global__ __launch_bounds__(128) void knn_kernel(
    const float* __restrict__ xyz1, const float* __restrict__ xyz2,
    int* __restrict__ knn_idx, float* __restrict__ knn_w)
{
    __shared__ float4 s2[N2_];
    const int tid = threadIdx.x;
    const int b   = blockIdx.y;
    const int n   = blockIdx.x * 32 + (tid >> 2);
    const int h   = tid & 3;

    for (int j = tid; j < N2_; j += 128) {
        float x = xyz2[((size_t)b * N2_ + j) * 3 + 0];
        float y = xyz2[((size_t)b * N2_ + j) * 3 + 1];
        float z = xyz2[((size_t)b * N2_ + j) * 3 + 2];
        s2[j] = make_float4(x, y, z, x * x + y * y + z * z);
    }
    __syncthreads();

    const float qx = xyz1[((size_t)b * N1_ + n) * 3 + 0];
    const float qy = xyz1[((size_t)b * N1_ + n) * 3 + 1];
    const float qz = xyz1[((size_t)b * N1_ + n) * 3 + 2];
    const float a2 = qx * qx + qy * qy + qz * qz;

    float d0 = 1e30f, d1 = 1e30f, d2v = 1e30f;
    int   i0 = 0, i1 = 0, i2 = 0;

    const int jbeg = h * (N2_ / 4);
    #pragma unroll 4
    for (int j = jbeg; j < jbeg + N2_ / 4; j++) {
        float4 c = s2[j];
        float ab = qx * c.x + qy * c.y + qz * c.z;
        float d  = fmaxf(fmaf(-2.0f, ab, a2 + c.w), 0.0f);
        if (d < d0) { d2v = d1; i2 = i1; d1 = d0; i1 = i0; d0 = d; i0 = j; }
        else if (d < d1) { d2v = d1; i2 = i1; d1 = d; i1 = j; }
        else if (d < d2v) { d2v = d; i2 = j; }
    }

    // two merge rounds: xor 1 then xor 2 (strict < keeps lower-half on ties)
    #pragma unroll
    for (int delta = 1; delta <= 2; delta <<= 1) {
        float od[3]; int oi[3];
        od[0] = __shfl_xor_sync(0xffffffffu, d0,  delta); oi[0] = __shfl_xor_sync(0xffffffffu, i0, delta);
        od[1] = __shfl_xor_sync(0xffffffffu, d1,  delta); oi[1] = __shfl_xor_sync(0xffffffffu, i1, delta);
        od[2] = __shfl_xor_sync(0xffffffffu, d2v, delta); oi[2] = __shfl_xor_sync(0xffffffffu, i2, delta);
        #pragma unroll
        for (int t = 0; t < 3; t++) {
            float d = od[t]; int i = oi[t];
            if (d < d0) { d2v = d1; i2 = i1; d1 = d0; i1 = i0; d0 = d; i0 = i; }
            else if (d < d1) { d2v = d1; i2 = i1; d1 = d; i1 = i; }
            else if (d < d2v) { d2v = d; i2 = i; }
        }
    }

    if (h == 0) {
        float w0 = 1.0f / (d0  + 1e-10f);
        float w1 = 1.0f / (d1  + 1e-10f);
        float w2 = 1.0f / (d2v + 1e-10f);
        float inv = 1.0f / (w0 + w1 + w2);
        const size_t gm = (size_t)b * N1_ + n;
        knn_idx[gm * 3 + 0] = b * N2_ + i0;
        knn_idx[gm * 3 + 1] = b * N2_ + i1;
        knn_idx[gm * 3 + 2] = b * N2_ + i2;
        knn_w[gm * 3 + 0] = w0 * inv;
        knn_w[gm * 3 + 1] = w1 * inv;
        knn_w[gm * 3 + 2] = w2 * inv;
    }
}

// ---------------------------------------------------------------------------
// fp32 -> fp16 cast ; weight transpose + fp16 cast
// ---------------------------------------------------------------------------
__global__ __launch_bounds__(256) void fcast_kernel(
    const float4* __restrict__ in, __half* __restrict__ o, int n4)
{
    int i = blockIdx.x * blockDim.x + threadIdx.x;
    if (i >= n4) return;
    float4 v = in[i];
    uint2 H = make_uint2(h2_bits(v.x, v.y), h2_bits(v.z, v.w));
    *(uint2*)(o + (size_t)i * 4) = H;
}

__global__ __launch_bounds__(256) void wcast_t_kernel(
    const float* __restrict__ W, int K, int N, __half* __restrict__ o)
{
    int i = blockIdx.x * blockDim.x + threadIdx.x;
    if (i >= N * K) return;
    int n = i / K, k = i % K;
    o[i] = __float2half_rn(W[(size_t)k * N + n]);
}

// ---------------------------------------------------------------------------
// warp-MMA fp16 GEMM, single term, 3-stage cp.async pipeline.
//   CTA tile 128x128, 8 warps (2m x 4n), warp tile 64x32, K-chunk 64.
// EPI: 0 raw fp16 -> Ch; 1 bias+relu+BN fp32 -> Cf;
//      2 +gather(fp16 Y2)+bias+relu+BN -> fp16 Ch
// ---------------------------------------------------------------------------
#define PLANE_B 16384                      // 128 rows x 128 bytes
#define STAGE_B (2 * PLANE_B)              // A, B
#define NSTAGE  3
#define GEMM_SMEM (NSTAGE * STAGE_B)       // 98304

__device__ __forceinline__ void load_plane(uint32_t dstBase,
                                           const __half* src,
                                           int rbase, int ld, int kc, int tid)
{
    #pragma unroll
    for (int i = 0; i < 4; i++) {
        int g   = i * 256 + tid;          // 1024 granules of 16B
        int row = g >> 3;
        int kb  = (g & 7) * 16;
        const char* s = (const char*)(src + (size_t)(rbase + row) * ld + kc) + kb;
        cp16(dstBase + swz((uint32_t)(row * 128 + kb)), s);
    }
}

template<int EPI>
__global__ __launch_bounds__(256, 2)
void gemm_mma(const __half* __restrict__ A, int lda,
              const __half* __restrict__ Bt, int ldb,
              int K,
              const float* __restrict__ bias, const float* __restrict__ gamma,
              const float* __restrict__ beta, const float* __restrict__ mean,
              const float* __restrict__ var,
              const __half* __restrict__ Y2,
              const int* __restrict__ kidx, const float* __restrict__ kw,
              float* __restrict__ Cf, __half* __restrict__ Ch,
              int N)
{
    extern __shared__ char smem[];
    const uint32_t sb = smem_u32(smem);
    const int tid  = threadIdx.x;
    const int wid  = tid >> 5;
    const int lane = tid & 31;
    const int wm   = wid >> 2;           // 0..1
    const int wn   = wid & 3;            // 0..3
    const int row0 = blockIdx.x * 128;
    const int col0 = blockIdx.y * 128;

    float acc[4][4][4];                  // [mb][nb][c0..c3]
    #pragma unroll
    for (int i = 0; i < 4; i++)
        #pragma unroll
        for (int j = 0; j < 4; j++)
            #pragma unroll
            for (int r = 0; r < 4; r++) acc[i][j][r] = 0.0f;

    const int a_row = (lane & 7) + ((lane >> 3) & 1) * 8;
    const int a_kb  = (lane >> 4) * 16;
    const int b_row = (lane & 7) + (lane >> 4) * 8;
    const int b_kb  = ((lane >> 3) & 1) * 16;

    uint32_t aoff[4], boff[2];
    #pragma unroll
    for (int mb = 0; mb < 4; mb++)
        aoff[mb] = (uint32_t)((wm * 64 + mb * 16 + a_row) * 128 + a_kb);
    #pragma unroll
    for (int p = 0; p < 2; p++)
        boff[p] = (uint32_t)((wn * 32 + p * 16 + b_row) * 128 + b_kb);

    const int nt = K >> 6;

    // prologue: issue stages 0 and 1
    load_plane(sb + 0 * STAGE_B + 0 * PLANE_B, A,  row0, lda, 0, tid);
    load_plane(sb + 0 * STAGE_B + 1 * PLANE_B, Bt, col0, ldb, 0, tid);
    cp_commit();
    if (nt > 1) {
        load_plane(sb + 1 * STAGE_B + 0 * PLANE_B, A,  row0, lda, 64, tid);
        load_plane(sb + 1 * STAGE_B + 1 * PLANE_B, Bt, col0, ldb, 64, tid);
        cp_commit();
    }

    for (int kt = 0; kt < nt; kt++) {
        const int stage = kt % NSTAGE;
        if (kt + 2 < nt) {
            const uint32_t s2b = sb + ((kt + 2) % NSTAGE) * STAGE_B;
            const int kc = (kt + 2) << 6;
            load_plane(s2b + 0 * PLANE_B, A,  row0, lda, kc, tid);
            load_plane(s2b + 1 * PLANE_B, Bt, col0, ldb, kc, tid);
            cp_commit();
            asm volatile("cp.async.wait_group 2;" ::: "memory");
        } else if (kt + 1 < nt) {
            asm volatile("cp.async.wait_group 1;" ::: "memory");
        } else {
            asm volatile("cp.async.wait_group 0;" ::: "memory");
        }
        __syncthreads();

        const uint32_t sA = sb + stage * STAGE_B + 0 * PLANE_B;
        const uint32_t sB = sb + stage * STAGE_B + 1 * PLANE_B;

        #pragma unroll
        for (int ks = 0; ks < 4; ks++) {
            const uint32_t kso = (uint32_t)(ks * 32);
            uint32_t aF[4][4], bF[4][2];
            #pragma unroll
            for (int p = 0; p < 2; p++) {
                ldsm4(bF[2 * p][0], bF[2 * p][1], bF[2 * p + 1][0], bF[2 * p + 1][1],
                      sB + swz(boff[p] + kso));
            }
            #pragma unroll
            for (int mb = 0; mb < 4; mb++)
                ldsm4(aF[mb][0], aF[mb][1], aF[mb][2], aF[mb][3],
                      sA + swz(aoff[mb] + kso));
            #pragma unroll
            for (int mb = 0; mb < 4; mb++)
                #pragma unroll
                for (int nb = 0; nb < 4; nb++)
                    mma16816(acc[mb][nb], aF[mb], bF[nb][0], bF[nb][1]);
        }
        __syncthreads();   // protect stage buffer before it is reloaded
    }

    // ----------------------------- epilogue --------------------------------
    float2 scv[4], shv[4], bbv[4];
    if (EPI != 0) {
        #pragma unroll
        for (int nb = 0; nb < 4; nb++) {
            int c = col0 + wn * 32 + nb * 8 + (lane & 3) * 2;
            float2 g  = *(const float2*)(gamma + c);
            float2 vv = *(const float2*)(var + c);
            float2 mn = *(const float2*)(mean + c);
            float2 bt = *(const float2*)(beta + c);
            float2 bs = *(const float2*)(bias + c);
            float s0 = g.x * rsqrtf(vv.x + BN_EPS);
            float s1 = g.y * rsqrtf(vv.y + BN_EPS);
            scv[nb] = make_float2(s0, s1);
            shv[nb] = make_float2(bt.x - mn.x * s0, bt.y - mn.y * s1);
            bbv[nb] = bs;
        }
    }

    #pragma unroll
    for (int mb = 0; mb < 4; mb++) {
        #pragma unroll
        for (int half = 0; half < 2; half++) {
            const int m = row0 + wm * 64 + mb * 16 + (lane >> 2) + half * 8;
            int gi0 = 0, gi1 = 0, gi2 = 0;
            float gw0 = 0.f, gw1 = 0.f, gw2 = 0.f;
            if (EPI == 2) {
                gi0 = kidx[(size_t)m * 3 + 0]; gw0 = kw[(size_t)m * 3 + 0];
                gi1 = kidx[(size_t)m * 3 + 1]; gw1 = kw[(size_t)m * 3 + 1];
                gi2 = kidx[(size_t)m * 3 + 2]; gw2 = kw[(size_t)m * 3 + 2];
            }
            #pragma unroll
            for (int nb = 0; nb < 4; nb++) {
                const int c = col0 + wn * 32 + nb * 8 + (lane & 3) * 2;
                float v0 = acc[mb][nb][half * 2 + 0];
                float v1 = acc[mb][nb][half * 2 + 1];
                if (EPI == 2) {
                    float2 y0 = __half22float2(*(const __half2*)(Y2 + (size_t)gi0 * CH_ + c));
                    float2 y1 = __half22float2(*(const __half2*)(Y2 + (size_t)gi1 * CH_ + c));
                    float2 y2v = __half22float2(*(const __half2*)(Y2 + (size_t)gi2 * CH_ + c));
                    v0 += gw0 * y0.x + gw1 * y1.x + gw2 * y2v.x;
                    v1 += gw0 * y0.y + gw1 * y1.y + gw2 * y2v.y;
                }
                if (EPI == 0) {
                    *(uint32_t*)(Ch + (size_t)m * N + c) = h2_bits(v0, v1);
                } else {
                    float z0 = fmaxf(v0 + bbv[nb].x, 0.0f);
                    float z1 = fmaxf(v1 + bbv[nb].y, 0.0f);
                    v0 = scv[nb].x * z0 + shv[nb].x;
                    v1 = scv[nb].y * z1 + shv[nb].y;
                    if (EPI == 1) {
                        *(float2*)(Cf + (size_t)m * N + c) = make_float2(v0, v1);
                    } else {
                        *(uint32_t*)(Ch + (size_t)m * N + c) = h2_bits(v0, v1);
                    }
                }
            }
        }
    }
}

// ---------------------------------------------------------------------------
// launch
// ---------------------------------------------------------------------------
extern "C" void kernel_launch(void* const* d_in, const int* in_sizes, int n_in,
                              void* d_out, int out_size)
{
    const float* xyz1   = (const float*)d_in[0];
    const float* xyz2   = (const float*)d_in[1];
    const float* feat1  = (const float*)d_in[2];
    const float* feat2  = (const float*)d_in[3];
    const float* W0     = (const float*)d_in[4];
    const float* b0     = (const float*)d_in[5];
    const float* gamma0 = (const float*)d_in[6];
    const float* beta0  = (const float*)d_in[7];
    const float* mean0  = (const float*)d_in[8];
    const float* var0   = (const float*)d_in[9];
    const float* W1     = (const float*)d_in[10];
    const float* b1     = (const float*)d_in[11];
    const float* gamma1 = (const float*)d_in[12];
    const float* beta1  = (const float*)d_in[13];
    const float* mean1  = (const float*)d_in[14];
    const float* var1   = (const float*)d_in[15];
    float* out = (float*)d_out;

    __half *y2, *x1, *f1, *f2, *w0t, *w1t;
    int *kidx; float *kw;
    cudaGetSymbolAddress((void**)&y2,   g_y2);
    cudaGetSymbolAddress((void**)&x1,   g_x1);
    cudaGetSymbolAddress((void**)&f1,   g_f1);
    cudaGetSymbolAddress((void**)&f2,   g_f2);
    cudaGetSymbolAddress((void**)&w0t,  g_w0t);
    cudaGetSymbolAddress((void**)&w1t,  g_w1t);
    cudaGetSymbolAddress((void**)&kidx, g_knn_idx);
    cudaGetSymbolAddress((void**)&kw,   g_knn_w);

    cudaFuncSetAttribute(gemm_mma<0>, cudaFuncAttributeMaxDynamicSharedMemorySize, GEMM_SMEM);
    cudaFuncSetAttribute(gemm_mma<1>, cudaFuncAttributeMaxDynamicSharedMemorySize, GEMM_SMEM);
    cudaFuncSetAttribute(gemm_mma<2>, cudaFuncAttributeMaxDynamicSharedMemorySize, GEMM_SMEM);

    // 1) 3-NN
    knn_kernel<<<dim3(N1_ / 32, B_), 128>>>(xyz1, xyz2, kidx, kw);

    // 2) weight transpose + fp16 cast
    wcast_t_kernel<<<(256 * 384 + 255) / 256, 256>>>(W0, 384, 256, w0t);
    wcast_t_kernel<<<(256 * 256 + 255) / 256, 256>>>(W1, 256, 256, w1t);

    // 3) feature fp16 casts
    {
        int n4 = M_ * C1_ / 4;
        fcast_kernel<<<(n4 + 255) / 256, 256>>>((const float4*)feat1, f1, n4);
    }
    {
        int n4 = M2_ * C2_ / 4;
        fcast_kernel<<<(n4 + 255) / 256, 256>>>((const float4*)feat2, f2, n4);
    }

    // 4) Y2 = feat2 @ W0[0:256]  (fp16 out)
    gemm_mma<0><<<dim3(M2_ / 128, CH_ / 128), 256, GEMM_SMEM>>>(
        f2, C2_, w0t, 384, 256,
        nullptr, nullptr, nullptr, nullptr, nullptr,
        nullptr, nullptr, nullptr,
        nullptr, y2, CH_);

    // 5) x1 = BN(relu(feat1 @ W0[256:384] + gather(Y2) + b0)) -> fp16
    gemm_mma<2><<<dim3(M_ / 128, CH_ / 128), 256, GEMM_SMEM>>>(
        f1, C1_, w0t + 256, 384, 128,
        b0, gamma0, beta0, mean0, var0,
        y2, kidx, kw,
        nullptr, x1, CH_);

    // 6) out = BN(relu(x1 @ W1 + b1))
    gemm_mma<1><<<dim3(M_ / 128, CH_ / 128), 256, GEMM_SMEM>>>(
        x1, CH_, w1t, 256, 256,
        b1, gamma1, beta1, mean1, var1,
        nullptr, nullptr, nullptr,
        out, nullptr, CH_);
}

// round 16
// speedup vs baseline: 1.0336x; 1.0336x over previous
#include <cuda_runtime.h>
#include <cuda_fp16.h>
#include <cuda_bf16.h>
#include <cstdint>

// ---------------------------------------------------------------------------
// FeaturePropagation, factorized + warp-MMA fp16 single-term (R14 GEMM shape)
//   knn:  3-NN idx+weights (4 threads/point)
//   Y2  = feat2 @ W0[0:256]                          (fp16, 8MB, L2-resident)
//   x1  = BN(relu(feat1 @ W0[256:384] + gather(Y2) + b0))  -> fp16 plane
//   out = BN(relu(x1 @ W1 + b1))                     (fp32)
// ---------------------------------------------------------------------------

#define B_   16
#define N1_  4096
#define N2_  1024
#define C1_  128
#define C2_  256
#define CH_  256
#define M_   (B_ * N1_)
#define M2_  (B_ * N2_)
#define BN_EPS 1e-3f

// ------------------------------- scratch ----------------------------------
__device__ __align__(16) __half g_y2[(size_t)M2_ * CH_];     // 8 MB
__device__ __align__(16) __half g_x1[(size_t)M_ * CH_];
__device__ __align__(16) __half g_f1[(size_t)M_ * C1_];
__device__ __align__(16) __half g_f2[(size_t)M2_ * C2_];
__device__ __align__(16) __half g_w0t[256 * 384];            // W0^T fp16
__device__ __align__(16) __half g_w1t[256 * 256];            // W1^T fp16
__device__ int   g_knn_idx[(size_t)M_ * 3];
__device__ float g_knn_w[(size_t)M_ * 3];

// ------------------------------ helpers -----------------------------------
__device__ __forceinline__ uint32_t smem_u32(const void* p) {
    uint32_t a;
    asm("{ .reg .u64 t; cvta.to.shared.u64 t, %1; cvt.u32.u64 %0, t; }"
        : "=r"(a) : "l"(p));
    return a;
}
__device__ __forceinline__ void cp16(uint32_t dst, const void* src) {
    asm volatile("cp.async.cg.shared.global [%0], [%1], 16;"
                 :: "r"(dst), "l"(src) : "memory");
}
__device__ __forceinline__ void cp_commit() {
    asm volatile("cp.async.commit_group;" ::: "memory");
}
__device__ __forceinline__ void ldsm4(uint32_t& r0, uint32_t& r1, uint32_t& r2,
                                      uint32_t& r3, uint32_t addr) {
    asm volatile("ldmatrix.sync.aligned.m8n8.x4.shared.b16 {%0,%1,%2,%3}, [%4];"
                 : "=r"(r0), "=r"(r1), "=r"(r2), "=r"(r3) : "r"(addr));
}
__device__ __forceinline__ void mma16816(float* c, const uint32_t* a,
                                         uint32_t b0, uint32_t b1) {
    asm volatile(
        "mma.sync.aligned.m16n8k16.row.col.f32.f16.f16.f32 "
        "{%0,%1,%2,%3}, {%4,%5,%6,%7}, {%8,%9}, {%0,%1,%2,%3};"
        : "+f"(c[0]), "+f"(c[1]), "+f"(c[2]), "+f"(c[3])
        : "r"(a[0]), "r"(a[1]), "r"(a[2]), "r"(a[3]), "r"(b0), "r"(b1));
}
__device__ __forceinline__ uint32_t swz(uint32_t off) {
    return off ^ ((off >> 3) & 0x70);
}
__device__ __forceinline__ uint32_t h2_bits(float lo, float hi) {
    __half2 v = __floats2half2_rn(lo, hi);
    return reinterpret_cast<uint32_t&>(v);
}

// ---------------------------------------------------------------------------
// Kernel 1: 3-NN search, 4 threads per point (2 shfl merge rounds).
// grid (N1/32, B), block 128.
// ---------------------------------------------------------------------------
__global__ __launch_bounds__(128) void knn_kernel(
    const float* __restrict__ xyz1, const float* __restrict__ xyz2,
    int* __restrict__ knn_idx, float* __restrict__ knn_w)
{
    __shared__ float4 s2[N2_];
    const int tid = threadIdx.x;
    const int b   = blockIdx.y;
    const int n   = blockIdx.x * 32 + (tid >> 2);
    const int h   = tid & 3;

    for (int j = tid; j < N2_; j += 128) {
        float x = xyz2[((size_t)b * N2_ + j) * 3 + 0];
        float y = xyz2[((size_t)b * N2_ + j) * 3 + 1];
        float z = xyz2[((size_t)b * N2_ + j) * 3 + 2];
        s2[j] = make_float4(x, y, z, x * x + y * y + z * z);
    }
    __syncthreads();

    const float qx = xyz1[((size_t)b * N1_ + n) * 3 + 0];
    const float qy = xyz1[((size_t)b * N1_ + n) * 3 + 1];
    const float qz = xyz1[((size_t)b * N1_ + n) * 3 + 2];
    const float a2 = qx * qx + qy * qy + qz * qz;

    float d0 = 1e30f, d1 = 1e30f, d2v = 1e30f;
    int   i0 = 0, i1 = 0, i2 = 0;

    const int jbeg = h * (N2_ / 4);
    #pragma unroll 4
    for (int j = jbeg; j < jbeg + N2_ / 4; j++) {
        float4 c = s2[j];
        float ab = qx * c.x + qy * c.y + qz * c.z;
        float d  = fmaxf(fmaf(-2.0f, ab, a2 + c.w), 0.0f);
        if (d < d0) { d2v = d1; i2 = i1; d1 = d0; i1 = i0; d0 = d; i0 = j; }
        else if (d < d1) { d2v = d1; i2 = i1; d1 = d; i1 = j; }
        else if (d < d2v) { d2v = d; i2 = j; }
    }

    // two merge rounds: xor 1 then xor 2 (strict < keeps lower-half on ties)
    #pragma unroll
    for (int delta = 1; delta <= 2; delta <<= 1) {
        float od[3]; int oi[3];
        od[0] = __shfl_xor_sync(0xffffffffu, d0,  delta); oi[0] = __shfl_xor_sync(0xffffffffu, i0, delta);
        od[1] = __shfl_xor_sync(0xffffffffu, d1,  delta); oi[1] = __shfl_xor_sync(0xffffffffu, i1, delta);
        od[2] = __shfl_xor_sync(0xffffffffu, d2v, delta); oi[2] = __shfl_xor_sync(0xffffffffu, i2, delta);
        #pragma unroll
        for (int t = 0; t < 3; t++) {
            float d = od[t]; int i = oi[t];
            if (d < d0) { d2v = d1; i2 = i1; d1 = d0; i1 = i0; d0 = d; i0 = i; }
            else if (d < d1) { d2v = d1; i2 = i1; d1 = d; i1 = i; }
            else if (d < d2v) { d2v = d; i2 = i; }
        }
    }

    if (h == 0) {
        float w0 = 1.0f / (d0  + 1e-10f);
        float w1 = 1.0f / (d1  + 1e-10f);
        float w2 = 1.0f / (d2v + 1e-10f);
        float inv = 1.0f / (w0 + w1 + w2);
        const size_t gm = (size_t)b * N1_ + n;
        knn_idx[gm * 3 + 0] = b * N2_ + i0;
        knn_idx[gm * 3 + 1] = b * N2_ + i1;
        knn_idx[gm * 3 + 2] = b * N2_ + i2;
        knn_w[gm * 3 + 0] = w0 * inv;
        knn_w[gm * 3 + 1] = w1 * inv;
        knn_w[gm * 3 + 2] = w2 * inv;
    }
}

// ---------------------------------------------------------------------------
// fp32 -> fp16 cast ; weight transpose + fp16 cast
// ---------------------------------------------------------------------------
__global__ __launch_bounds__(256) void fcast_kernel(
    const float4* __restrict__ in, __half* __restrict__ o, int n4)
{
    int i = blockIdx.x * blockDim.x + threadIdx.x;
    if (i >= n4) return;
    float4 v = in[i];
    uint2 H = make_uint2(h2_bits(v.x, v.y), h2_bits(v.z, v.w));
    *(uint2*)(o + (size_t)i * 4) = H;
}

__global__ __launch_bounds__(256) void wcast_t_kernel(
    const float* __restrict__ W, int K, int N, __half* __restrict__ o)
{
    int i = blockIdx.x * blockDim.x + threadIdx.x;
    if (i >= N * K) return;
    int n = i / K, k = i % K;
    o[i] = __float2half_rn(W[(size_t)k * N + n]);
}

// ---------------------------------------------------------------------------
// warp-MMA fp16 GEMM, single term, 2-stage cp.async (R14-proven shape).
//   CTA tile 128x128, 8 warps (2m x 4n), warp tile 64x32, K-chunk 64.
// EPI: 0 raw fp16 -> Ch; 1 bias+relu+BN fp32 -> Cf;
//      2 +gather(fp16 Y2)+bias+relu+BN -> fp16 Ch
// ---------------------------------------------------------------------------
#define PLANE_B 16384                      // 128 rows x 128 bytes
#define STAGE_B (2 * PLANE_B)              // A, B
#define GEMM_SMEM (2 * STAGE_B)            // 65536

__device__ __forceinline__ void load_plane(uint32_t dstBase,
                                           const __half* src,
                                           int rbase, int ld, int kc, int tid)
{
    #pragma unroll
    for (int i = 0; i < 4; i++) {
        int g   = i * 256 + tid;          // 1024 granules of 16B
        int row = g >> 3;
        int kb  = (g & 7) * 16;
        const char* s = (const char*)(src + (size_t)(rbase + row) * ld + kc) + kb;
        cp16(dstBase + swz((uint32_t)(row * 128 + kb)), s);
    }
}

template<int EPI>
__global__ __launch_bounds__(256)
void gemm_mma(const __half* __restrict__ A, int lda,
              const __half* __restrict__ Bt, int ldb,
              int K,
              const float* __restrict__ bias, const float* __restrict__ gamma,
              const float* __restrict__ beta, const float* __restrict__ mean,
              const float* __restrict__ var,
              const __half* __restrict__ Y2,
              const int* __restrict__ kidx, const float* __restrict__ kw,
              float* __restrict__ Cf, __half* __restrict__ Ch,
              int N)
{
    extern __shared__ char smem[];
    const uint32_t sb = smem_u32(smem);
    const int tid  = threadIdx.x;
    const int wid  = tid >> 5;
    const int lane = tid & 31;
    const int wm   = wid >> 2;           // 0..1
    const int wn   = wid & 3;            // 0..3
    const int row0 = blockIdx.x * 128;
    const int col0 = blockIdx.y * 128;

    float acc[4][4][4];                  // [mb][nb][c0..c3]
    #pragma unroll
    for (int i = 0; i < 4; i++)
        #pragma unroll
        for (int j = 0; j < 4; j++)
            #pragma unroll
            for (int r = 0; r < 4; r++) acc[i][j][r] = 0.0f;

    const int a_row = (lane & 7) + ((lane >> 3) & 1) * 8;
    const int a_kb  = (lane >> 4) * 16;
    const int b_row = (lane & 7) + (lane >> 4) * 8;
    const int b_kb  = ((lane >> 3) & 1) * 16;

    uint32_t aoff[4], boff[2];
    #pragma unroll
    for (int mb = 0; mb < 4; mb++)
        aoff[mb] = (uint32_t)((wm * 64 + mb * 16 + a_row) * 128 + a_kb);
    #pragma unroll
    for (int p = 0; p < 2; p++)
        boff[p] = (uint32_t)((wn * 32 + p * 16 + b_row) * 128 + b_kb);

    const int nt = K >> 6;

    // prologue
    load_plane(sb + 0 * STAGE_B + 0 * PLANE_B, A,  row0, lda, 0, tid);
    load_plane(sb + 0 * STAGE_B + 1 * PLANE_B, Bt, col0, ldb, 0, tid);
    cp_commit();

    for (int kt = 0; kt < nt; kt++) {
        const int stage = kt & 1;
        if (kt + 1 < nt) {
            const uint32_t s2b = sb + (stage ^ 1) * STAGE_B;
            const int kc = (kt + 1) << 6;
            load_plane(s2b + 0 * PLANE_B, A,  row0, lda, kc, tid);
            load_plane(s2b + 1 * PLANE_B, Bt, col0, ldb, kc, tid);
            cp_commit();
            asm volatile("cp.async.wait_group 1;" ::: "memory");
        } else {
            asm volatile("cp.async.wait_group 0;" ::: "memory");
        }
        __syncthreads();

        const uint32_t sA = sb + stage * STAGE_B + 0 * PLANE_B;
        const uint32_t sB = sb + stage * STAGE_B + 1 * PLANE_B;

        #pragma unroll
        for (int ks = 0; ks < 4; ks++) {
            const uint32_t kso = (uint32_t)(ks * 32);
            uint32_t aF[4][4], bF[4][2];
            #pragma unroll
            for (int p = 0; p < 2; p++) {
                ldsm4(bF[2 * p][0], bF[2 * p][1], bF[2 * p + 1][0], bF[2 * p + 1][1],
                      sB + swz(boff[p] + kso));
            }
            #pragma unroll
            for (int mb = 0; mb < 4; mb++)
                ldsm4(aF[mb][0], aF[mb][1], aF[mb][2], aF[mb][3],
                      sA + swz(aoff[mb] + kso));
            #pragma unroll
            for (int mb = 0; mb < 4; mb++)
                #pragma unroll
                for (int nb = 0; nb < 4; nb++)
                    mma16816(acc[mb][nb], aF[mb], bF[nb][0], bF[nb][1]);
        }
        __syncthreads();
    }

    // ----------------------------- epilogue --------------------------------
    float2 scv[4], shv[4], bbv[4];
    if (EPI != 0) {
        #pragma unroll
        for (int nb = 0; nb < 4; nb++) {
            int c = col0 + wn * 32 + nb * 8 + (lane & 3) * 2;
            float2 g  = *(const float2*)(gamma + c);
            float2 vv = *(const float2*)(var + c);
            float2 mn = *(const float2*)(mean + c);
            float2 bt = *(const float2*)(beta + c);
            float2 bs = *(const float2*)(bias + c);
            float s0 = g.x * rsqrtf(vv.x + BN_EPS);
            float s1 = g.y * rsqrtf(vv.y + BN_EPS);
            scv[nb] = make_float2(s0, s1);
            shv[nb] = make_float2(bt.x - mn.x * s0, bt.y - mn.y * s1);
            bbv[nb] = bs;
        }
    }

    #pragma unroll
    for (int mb = 0; mb < 4; mb++) {
        #pragma unroll
        for (int half = 0; half < 2; half++) {
            const int m = row0 + wm * 64 + mb * 16 + (lane >> 2) + half * 8;
            int gi0 = 0, gi1 = 0, gi2 = 0;
            float gw0 = 0.f, gw1 = 0.f, gw2 = 0.f;
            if (EPI == 2) {
                gi0 = kidx[(size_t)m * 3 + 0]; gw0 = kw[(size_t)m * 3 + 0];
                gi1 = kidx[(size_t)m * 3 + 1]; gw1 = kw[(size_t)m * 3 + 1];
                gi2 = kidx[(size_t)m * 3 + 2]; gw2 = kw[(size_t)m * 3 + 2];
            }
            #pragma unroll
            for (int nb = 0; nb < 4; nb++) {
                const int c = col0 + wn * 32 + nb * 8 + (lane & 3) * 2;
                float v0 = acc[mb][nb][half * 2 + 0];
                float v1 = acc[mb][nb][half * 2 + 1];
                if (EPI == 2) {
                    float2 y0 = __half22float2(*(const __half2*)(Y2 + (size_t)gi0 * CH_ + c));
                    float2 y1 = __half22float2(*(const __half2*)(Y2 + (size_t)gi1 * CH_ + c));
                    float2 y2v = __half22float2(*(const __half2*)(Y2 + (size_t)gi2 * CH_ + c));
                    v0 += gw0 * y0.x + gw1 * y1.x + gw2 * y2v.x;
                    v1 += gw0 * y0.y + gw1 * y1.y + gw2 * y2v.y;
                }
                if (EPI == 0) {
                    *(uint32_t*)(Ch + (size_t)m * N + c) = h2_bits(v0, v1);
                } else {
                    float z0 = fmaxf(v0 + bbv[nb].x, 0.0f);
                    float z1 = fmaxf(v1 + bbv[nb].y, 0.0f);
                    v0 = scv[nb].x * z0 + shv[nb].x;
                    v1 = scv[nb].y * z1 + shv[nb].y;
                    if (EPI == 1) {
                        *(float2*)(Cf + (size_t)m * N + c) = make_float2(v0, v1);
                    } else {
                        *(uint32_t*)(Ch + (size_t)m * N + c) = h2_bits(v0, v1);
                    }
                }
            }
        }
    }
}

// ---------------------------------------------------------------------------
// launch
// ---------------------------------------------------------------------------
extern "C" void kernel_launch(void* const* d_in, const int* in_sizes, int n_in,
                              void* d_out, int out_size)
{
    const float* xyz1   = (const float*)d_in[0];
    const float* xyz2   = (const float*)d_in[1];
    const float* feat1  = (const float*)d_in[2];
    const float* feat2  = (const float*)d_in[3];
    const float* W0     = (const float*)d_in[4];
    const float* b0     = (const float*)d_in[5];
    const float* gamma0 = (const float*)d_in[6];
    const float* beta0  = (const float*)d_in[7];
    const float* mean0  = (const float*)d_in[8];
    const float* var0   = (const float*)d_in[9];
    const float* W1     = (const float*)d_in[10];
    const float* b1     = (const float*)d_in[11];
    const float* gamma1 = (const float*)d_in[12];
    const float* beta1  = (const float*)d_in[13];
    const float* mean1  = (const float*)d_in[14];
    const float* var1   = (const float*)d_in[15];
    float* out = (float*)d_out;

    __half *y2, *x1, *f1, *f2, *w0t, *w1t;
    int *kidx; float *kw;
    cudaGetSymbolAddress((void**)&y2,   g_y2);
    cudaGetSymbolAddress((void**)&x1,   g_x1);
    cudaGetSymbolAddress((void**)&f1,   g_f1);
    cudaGetSymbolAddress((void**)&f2,   g_f2);
    cudaGetSymbolAddress((void**)&w0t,  g_w0t);
    cudaGetSymbolAddress((void**)&w1t,  g_w1t);
    cudaGetSymbolAddress((void**)&kidx, g_knn_idx);
    cudaGetSymbolAddress((void**)&kw,   g_knn_w);

    cudaFuncSetAttribute(gemm_mma<0>, cudaFuncAttributeMaxDynamicSharedMemorySize, GEMM_SMEM);
    cudaFuncSetAttribute(gemm_mma<1>, cudaFuncAttributeMaxDynamicSharedMemorySize, GEMM_SMEM);
    cudaFuncSetAttribute(gemm_mma<2>, cudaFuncAttributeMaxDynamicSharedMemorySize, GEMM_SMEM);

    // 1) 3-NN
    knn_kernel<<<dim3(N1_ / 32, B_), 128>>>(xyz1, xyz2, kidx, kw);

    // 2) weight transpose + fp16 cast
    wcast_t_kernel<<<(256 * 384 + 255) / 256, 256>>>(W0, 384, 256, w0t);
    wcast_t_kernel<<<(256 * 256 + 255) / 256, 256>>>(W1, 256, 256, w1t);

    // 3) feature fp16 casts
    {
        int n4 = M_ * C1_ / 4;
        fcast_kernel<<<(n4 + 255) / 256, 256>>>((const float4*)feat1, f1, n4);
    }
    {
        int n4 = M2_ * C2_ / 4;
        fcast_kernel<<<(n4 + 255) / 256, 256>>>((const float4*)feat2, f2, n4);
    }

    // 4) Y2 = feat2 @ W0[0:256]  (fp16 out)
    gemm_mma<0><<<dim3(M2_ / 128, CH_ / 128), 256, GEMM_SMEM>>>(
        f2, C2_, w0t, 384, 256,
        nullptr, nullptr, nullptr, nullptr, nullptr,
        nullptr, nullptr, nullptr,
        nullptr, y2, CH_);

    // 5) x1 = BN(relu(feat1 @ W0[256:384] + gather(Y2) + b0)) -> fp16
    gemm_mma<2><<<dim3(M_ / 128, CH_ / 128), 256, GEMM_SMEM>>>(
        f1, C1_, w0t + 256, 384, 128,
        b0, gamma0, beta0, mean0, var0,
        y2, kidx, kw,
        nullptr, x1, CH_);

    // 6) out = BN(relu(x1 @ W1 + b1))
    gemm_mma<1><<<dim3(M_ / 128, CH_ / 128), 256, GEMM_SMEM>>>(
        x1, CH_, w1t, 256, 256,
        b1, gamma1, beta1, mean1, var1,
        nullptr, nullptr, nullptr,
        out, nullptr, CH_);
}

// round 17
// speedup vs baseline: 1.3117x; 1.2691x over previous
#include <cuda_runtime.h>
#include <cuda_fp16.h>
#include <cuda_bf16.h>
#include <cstdint>

// ---------------------------------------------------------------------------
// FeaturePropagation, factorized + warp-MMA fp16 single-term, 3-stage pipeline
//   knn:  3-NN idx+weights (2 threads/point — R14-proven)
//   Y2  = feat2 @ W0[0:256]                          (fp32, 16MB, L2-resident)
//   x1  = BN(relu(feat1 @ W0[256:384] + gather(Y2) + b0))  -> fp16 plane
//   out = BN(relu(x1 @ W1 + b1))                     (fp32)
// ---------------------------------------------------------------------------

#define B_   16
#define N1_  4096
#define N2_  1024
#define C1_  128
#define C2_  256
#define CH_  256
#define M_   (B_ * N1_)
#define M2_  (B_ * N2_)
#define BN_EPS 1e-3f

// ------------------------------- scratch ----------------------------------
__device__ __align__(16) float g_y2[(size_t)M2_ * CH_];      // 16 MB
__device__ __align__(16) __half g_x1[(size_t)M_ * CH_];
__device__ __align__(16) __half g_f1[(size_t)M_ * C1_];
__device__ __align__(16) __half g_f2[(size_t)M2_ * C2_];
__device__ __align__(16) __half g_w0t[256 * 384];            // W0^T fp16
__device__ __align__(16) __half g_w1t[256 * 256];            // W1^T fp16
__device__ int   g_knn_idx[(size_t)M_ * 3];
__device__ float g_knn_w[(size_t)M_ * 3];

// ------------------------------ helpers -----------------------------------
__device__ __forceinline__ uint32_t smem_u32(const void* p) {
    uint32_t a;
    asm("{ .reg .u64 t; cvta.to.shared.u64 t, %1; cvt.u32.u64 %0, t; }"
        : "=r"(a) : "l"(p));
    return a;
}
__device__ __forceinline__ void cp16(uint32_t dst, const void* src) {
    asm volatile("cp.async.cg.shared.global [%0], [%1], 16;"
                 :: "r"(dst), "l"(src) : "memory");
}
__device__ __forceinline__ void cp_commit() {
    asm volatile("cp.async.commit_group;" ::: "memory");
}
__device__ __forceinline__ void ldsm4(uint32_t& r0, uint32_t& r1, uint32_t& r2,
                                      uint32_t& r3, uint32_t addr) {
    asm volatile("ldmatrix.sync.aligned.m8n8.x4.shared.b16 {%0,%1,%2,%3}, [%4];"
                 : "=r"(r0), "=r"(r1), "=r"(r2), "=r"(r3) : "r"(addr));
}
__device__ __forceinline__ void mma16816(float* c, const uint32_t* a,
                                         uint32_t b0, uint32_t b1) {
    asm volatile(
        "mma.sync.aligned.m16n8k16.row.col.f32.f16.f16.f32 "
        "{%0,%1,%2,%3}, {%4,%5,%6,%7}, {%8,%9}, {%0,%1,%2,%3};"
        : "+f"(c[0]), "+f"(c[1]), "+f"(c[2]), "+f"(c[3])
        : "r"(a[0]), "r"(a[1]), "r"(a[2]), "r"(a[3]), "r"(b0), "r"(b1));
}
__device__ __forceinline__ uint32_t swz(uint32_t off) {
    return off ^ ((off >> 3) & 0x70);
}
__device__ __forceinline__ uint32_t h2_bits(float lo, float hi) {
    __half2 v = __floats2half2_rn(lo, hi);
    return reinterpret_cast<uint32_t&>(v);
}

// ---------------------------------------------------------------------------
// Kernel 1: 3-NN search, 2 threads per point (R14-proven).
// grid (N1/64, B), block 128.
// ---------------------------------------------------------------------------
#define KPB 64

__global__ __launch_bounds__(128) void knn_kernel(
    const float* __restrict__ xyz1, const float* __restrict__ xyz2,
    int* __restrict__ knn_idx, float* __restrict__ knn_w)
{
    __shared__ float4 s2[N2_];
    const int tid = threadIdx.x;
    const int b   = blockIdx.y;
    const int n   = blockIdx.x * KPB + (tid >> 1);
    const int h   = tid & 1;

    for (int j = tid; j < N2_; j += 128) {
        float x = xyz2[((size_t)b * N2_ + j) * 3 + 0];
        float y = xyz2[((size_t)b * N2_ + j) * 3 + 1];
        float z = xyz2[((size_t)b * N2_ + j) * 3 + 2];
        s2[j] = make_float4(x, y, z, x * x + y * y + z * z);
    }
    __syncthreads();

    const float qx = xyz1[((size_t)b * N1_ + n) * 3 + 0];
    const float qy = xyz1[((size_t)b * N1_ + n) * 3 + 1];
    const float qz = xyz1[((size_t)b * N1_ + n) * 3 + 2];
    const float a2 = qx * qx + qy * qy + qz * qz;

    float d0 = 1e30f, d1 = 1e30f, d2v = 1e30f;
    int   i0 = 0, i1 = 0, i2 = 0;

    const int jbeg = h * (N2_ / 2);
    #pragma unroll 4
    for (int j = jbeg; j < jbeg + N2_ / 2; j++) {
        float4 c = s2[j];
        float ab = qx * c.x + qy * c.y + qz * c.z;
        float d  = fmaxf(fmaf(-2.0f, ab, a2 + c.w), 0.0f);
        if (d < d0) { d2v = d1; i2 = i1; d1 = d0; i1 = i0; d0 = d; i0 = j; }
        else if (d < d1) { d2v = d1; i2 = i1; d1 = d; i1 = j; }
        else if (d < d2v) { d2v = d; i2 = j; }
    }

    float od[3]; int oi[3];
    od[0] = __shfl_xor_sync(0xffffffffu, d0,  1); oi[0] = __shfl_xor_sync(0xffffffffu, i0, 1);
    od[1] = __shfl_xor_sync(0xffffffffu, d1,  1); oi[1] = __shfl_xor_sync(0xffffffffu, i1, 1);
    od[2] = __shfl_xor_sync(0xffffffffu, d2v, 1); oi[2] = __shfl_xor_sync(0xffffffffu, i2, 1);
    #pragma unroll
    for (int t = 0; t < 3; t++) {
        float d = od[t]; int i = oi[t];
        if (d < d0) { d2v = d1; i2 = i1; d1 = d0; i1 = i0; d0 = d; i0 = i; }
        else if (d < d1) { d2v = d1; i2 = i1; d1 = d; i1 = i; }
        else if (d < d2v) { d2v = d; i2 = i; }
    }

    if (h == 0) {
        float w0 = 1.0f / (d0  + 1e-10f);
        float w1 = 1.0f / (d1  + 1e-10f);
        float w2 = 1.0f / (d2v + 1e-10f);
        float inv = 1.0f / (w0 + w1 + w2);
        const size_t gm = (size_t)b * N1_ + n;
        knn_idx[gm * 3 + 0] = b * N2_ + i0;
        knn_idx[gm * 3 + 1] = b * N2_ + i1;
        knn_idx[gm * 3 + 2] = b * N2_ + i2;
        knn_w[gm * 3 + 0] = w0 * inv;
        knn_w[gm * 3 + 1] = w1 * inv;
        knn_w[gm * 3 + 2] = w2 * inv;
    }
}

// ---------------------------------------------------------------------------
// fp32 -> fp16 cast ; weight transpose + fp16 cast
// ---------------------------------------------------------------------------
__global__ __launch_bounds__(256) void fcast_kernel(
    const float4* __restrict__ in, __half* __restrict__ o, int n4)
{
    int i = blockIdx.x * blockDim.x + threadIdx.x;
    if (i >= n4) return;
    float4 v = in[i];
    uint2 H = make_uint2(h2_bits(v.x, v.y), h2_bits(v.z, v.w));
    *(uint2*)(o + (size_t)i * 4) = H;
}

__global__ __launch_bounds__(256) void wcast_t_kernel(
    const float* __restrict__ W, int K, int N, __half* __restrict__ o)
{
    int i = blockIdx.x * blockDim.x + threadIdx.x;
    if (i >= N * K) return;
    int n = i / K, k = i % K;
    o[i] = __float2half_rn(W[(size_t)k * N + n]);
}

// ---------------------------------------------------------------------------
// warp-MMA fp16 GEMM, single term, 3-stage cp.async, ONE sync per chunk
// (sync BEFORE prefetch-issue => stage reuse is barrier-protected).
//   CTA tile 128x128, 8 warps (2m x 4n), warp tile 64x32, K-chunk 64.
// EPI: 0 raw fp32 -> Cf; 1 bias+relu+BN fp32 -> Cf;
//      2 +gather(fp32 Y2)+bias+relu+BN -> fp16 Ch
// ---------------------------------------------------------------------------
#define PLANE_B 16384                      // 128 rows x 128 bytes
#define STAGE_B (2 * PLANE_B)              // A, B
#define NSTAGE  3
#define GEMM_SMEM (NSTAGE * STAGE_B)       // 98304

__device__ __forceinline__ void load_plane(uint32_t dstBase,
                                           const __half* src,
                                           int rbase, int ld, int kc, int tid)
{
    #pragma unroll
    for (int i = 0; i < 4; i++) {
        int g   = i * 256 + tid;          // 1024 granules of 16B
        int row = g >> 3;
        int kb  = (g & 7) * 16;
        const char* s = (const char*)(src + (size_t)(rbase + row) * ld + kc) + kb;
        cp16(dstBase + swz((uint32_t)(row * 128 + kb)), s);
    }
}

template<int EPI>
__global__ __launch_bounds__(256)
void gemm_mma(const __half* __restrict__ A, int lda,
              const __half* __restrict__ Bt, int ldb,
              int K,
              const float* __restrict__ bias, const float* __restrict__ gamma,
              const float* __restrict__ beta, const float* __restrict__ mean,
              const float* __restrict__ var,
              const float* __restrict__ Y2,
              const int* __restrict__ kidx, const float* __restrict__ kw,
              float* __restrict__ Cf, __half* __restrict__ Ch,
              int N)
{
    extern __shared__ char smem[];
    const uint32_t sb = smem_u32(smem);
    const int tid  = threadIdx.x;
    const int wid  = tid >> 5;
    const int lane = tid & 31;
    const int wm   = wid >> 2;           // 0..1
    const int wn   = wid & 3;            // 0..3
    const int row0 = blockIdx.x * 128;
    const int col0 = blockIdx.y * 128;

    float acc[4][4][4];                  // [mb][nb][c0..c3]
    #pragma unroll
    for (int i = 0; i < 4; i++)
        #pragma unroll
        for (int j = 0; j < 4; j++)
            #pragma unroll
            for (int r = 0; r < 4; r++) acc[i][j][r] = 0.0f;

    const int a_row = (lane & 7) + ((lane >> 3) & 1) * 8;
    const int a_kb  = (lane >> 4) * 16;
    const int b_row = (lane & 7) + (lane >> 4) * 8;
    const int b_kb  = ((lane >> 3) & 1) * 16;

    uint32_t aoff[4], boff[2];
    #pragma unroll
    for (int mb = 0; mb < 4; mb++)
        aoff[mb] = (uint32_t)((wm * 64 + mb * 16 + a_row) * 128 + a_kb);
    #pragma unroll
    for (int p = 0; p < 2; p++)
        boff[p] = (uint32_t)((wn * 32 + p * 16 + b_row) * 128 + b_kb);

    const int nt = K >> 6;

    // prologue: stages 0 and 1 in flight
    load_plane(sb + 0 * STAGE_B + 0 * PLANE_B, A,  row0, lda, 0, tid);
    load_plane(sb + 0 * STAGE_B + 1 * PLANE_B, Bt, col0, ldb, 0, tid);
    cp_commit();
    if (nt > 1) {
        load_plane(sb + 1 * STAGE_B + 0 * PLANE_B, A,  row0, lda, 64, tid);
        load_plane(sb + 1 * STAGE_B + 1 * PLANE_B, Bt, col0, ldb, 64, tid);
        cp_commit();
    }

    int stage = 0;       // kt % 3
    int pstage = 2;      // (kt + 2) % 3
    for (int kt = 0; kt < nt; kt++) {
        // complete chunk kt's copies, then barrier (covers stage-reuse too)
        if (kt + 1 < nt) {
            asm volatile("cp.async.wait_group 1;" ::: "memory");
        } else {
            asm volatile("cp.async.wait_group 0;" ::: "memory");
        }
        __syncthreads();

        // prefetch chunk kt+2 into stage (kt+2)%3 (last read at iter kt-1,
        // all readers passed the barrier above)
        if (kt + 2 < nt) {
            const uint32_t s2b = sb + (uint32_t)pstage * STAGE_B;
            const int kc = (kt + 2) << 6;
            load_plane(s2b + 0 * PLANE_B, A,  row0, lda, kc, tid);
            load_plane(s2b + 1 * PLANE_B, Bt, col0, ldb, kc, tid);
            cp_commit();
        }

        const uint32_t sA = sb + (uint32_t)stage * STAGE_B + 0 * PLANE_B;
        const uint32_t sB = sb + (uint32_t)stage * STAGE_B + 1 * PLANE_B;

        #pragma unroll
        for (int ks = 0; ks < 4; ks++) {
            const uint32_t kso = (uint32_t)(ks * 32);
            uint32_t aF[4][4], bF[4][2];
            #pragma unroll
            for (int p = 0; p < 2; p++) {
                ldsm4(bF[2 * p][0], bF[2 * p][1], bF[2 * p + 1][0], bF[2 * p + 1][1],
                      sB + swz(boff[p] + kso));
            }
            #pragma unroll
            for (int mb = 0; mb < 4; mb++)
                ldsm4(aF[mb][0], aF[mb][1], aF[mb][2], aF[mb][3],
                      sA + swz(aoff[mb] + kso));
            #pragma unroll
            for (int mb = 0; mb < 4; mb++)
                #pragma unroll
                for (int nb = 0; nb < 4; nb++)
                    mma16816(acc[mb][nb], aF[mb], bF[nb][0], bF[nb][1]);
        }

        stage  = (stage  == NSTAGE - 1) ? 0 : stage + 1;
        pstage = (pstage == NSTAGE - 1) ? 0 : pstage + 1;
    }

    // ----------------------------- epilogue --------------------------------
    float2 scv[4], shv[4], bbv[4];
    if (EPI != 0) {
        #pragma unroll
        for (int nb = 0; nb < 4; nb++) {
            int c = col0 + wn * 32 + nb * 8 + (lane & 3) * 2;
            float2 g  = *(const float2*)(gamma + c);
            float2 vv = *(const float2*)(var + c);
            float2 mn = *(const float2*)(mean + c);
            float2 bt = *(const float2*)(beta + c);
            float2 bs = *(const float2*)(bias + c);
            float s0 = g.x * rsqrtf(vv.x + BN_EPS);
            float s1 = g.y * rsqrtf(vv.y + BN_EPS);
            scv[nb] = make_float2(s0, s1);
            shv[nb] = make_float2(bt.x - mn.x * s0, bt.y - mn.y * s1);
            bbv[nb] = bs;
        }
    }

    #pragma unroll
    for (int mb = 0; mb < 4; mb++) {
        #pragma unroll
        for (int half = 0; half < 2; half++) {
            const int m = row0 + wm * 64 + mb * 16 + (lane >> 2) + half * 8;
            int gi0 = 0, gi1 = 0, gi2 = 0;
            float gw0 = 0.f, gw1 = 0.f, gw2 = 0.f;
            if (EPI == 2) {
                gi0 = kidx[(size_t)m * 3 + 0]; gw0 = kw[(size_t)m * 3 + 0];
                gi1 = kidx[(size_t)m * 3 + 1]; gw1 = kw[(size_t)m * 3 + 1];
                gi2 = kidx[(size_t)m * 3 + 2]; gw2 = kw[(size_t)m * 3 + 2];
            }
            #pragma unroll
            for (int nb = 0; nb < 4; nb++) {
                const int c = col0 + wn * 32 + nb * 8 + (lane & 3) * 2;
                float v0 = acc[mb][nb][half * 2 + 0];
                float v1 = acc[mb][nb][half * 2 + 1];
                if (EPI == 2) {
                    float2 y0 = *(const float2*)(Y2 + (size_t)gi0 * CH_ + c);
                    float2 y1 = *(const float2*)(Y2 + (size_t)gi1 * CH_ + c);
                    float2 y2v = *(const float2*)(Y2 + (size_t)gi2 * CH_ + c);
                    v0 += gw0 * y0.x + gw1 * y1.x + gw2 * y2v.x;
                    v1 += gw0 * y0.y + gw1 * y1.y + gw2 * y2v.y;
                }
                if (EPI == 0) {
                    *(float2*)(Cf + (size_t)m * N + c) = make_float2(v0, v1);
                } else {
                    float z0 = fmaxf(v0 + bbv[nb].x, 0.0f);
                    float z1 = fmaxf(v1 + bbv[nb].y, 0.0f);
                    v0 = scv[nb].x * z0 + shv[nb].x;
                    v1 = scv[nb].y * z1 + shv[nb].y;
                    if (EPI == 1) {
                        *(float2*)(Cf + (size_t)m * N + c) = make_float2(v0, v1);
                    } else {
                        *(uint32_t*)(Ch + (size_t)m * N + c) = h2_bits(v0, v1);
                    }
                }
            }
        }
    }
}

// ---------------------------------------------------------------------------
// launch
// ---------------------------------------------------------------------------
extern "C" void kernel_launch(void* const* d_in, const int* in_sizes, int n_in,
                              void* d_out, int out_size)
{
    const float* xyz1   = (const float*)d_in[0];
    const float* xyz2   = (const float*)d_in[1];
    const float* feat1  = (const float*)d_in[2];
    const float* feat2  = (const float*)d_in[3];
    const float* W0     = (const float*)d_in[4];
    const float* b0     = (const float*)d_in[5];
    const float* gamma0 = (const float*)d_in[6];
    const float* beta0  = (const float*)d_in[7];
    const float* mean0  = (const float*)d_in[8];
    const float* var0   = (const float*)d_in[9];
    const float* W1     = (const float*)d_in[10];
    const float* b1     = (const float*)d_in[11];
    const float* gamma1 = (const float*)d_in[12];
    const float* beta1  = (const float*)d_in[13];
    const float* mean1  = (const float*)d_in[14];
    const float* var1   = (const float*)d_in[15];
    float* out = (float*)d_out;

    float *y2; __half *x1, *f1, *f2, *w0t, *w1t;
    int *kidx; float *kw;
    cudaGetSymbolAddress((void**)&y2,   g_y2);
    cudaGetSymbolAddress((void**)&x1,   g_x1);
    cudaGetSymbolAddress((void**)&f1,   g_f1);
    cudaGetSymbolAddress((void**)&f2,   g_f2);
    cudaGetSymbolAddress((void**)&w0t,  g_w0t);
    cudaGetSymbolAddress((void**)&w1t,  g_w1t);
    cudaGetSymbolAddress((void**)&kidx, g_knn_idx);
    cudaGetSymbolAddress((void**)&kw,   g_knn_w);

    cudaFuncSetAttribute(gemm_mma<0>, cudaFuncAttributeMaxDynamicSharedMemorySize, GEMM_SMEM);
    cudaFuncSetAttribute(gemm_mma<1>, cudaFuncAttributeMaxDynamicSharedMemorySize, GEMM_SMEM);
    cudaFuncSetAttribute(gemm_mma<2>, cudaFuncAttributeMaxDynamicSharedMemorySize, GEMM_SMEM);

    // 1) 3-NN
    knn_kernel<<<dim3(N1_ / KPB, B_), 128>>>(xyz1, xyz2, kidx, kw);

    // 2) weight transpose + fp16 cast
    wcast_t_kernel<<<(256 * 384 + 255) / 256, 256>>>(W0, 384, 256, w0t);
    wcast_t_kernel<<<(256 * 256 + 255) / 256, 256>>>(W1, 256, 256, w1t);

    // 3) feature fp16 casts
    {
        int n4 = M_ * C1_ / 4;
        fcast_kernel<<<(n4 + 255) / 256, 256>>>((const float4*)feat1, f1, n4);
    }
    {
        int n4 = M2_ * C2_ / 4;
        fcast_kernel<<<(n4 + 255) / 256, 256>>>((const float4*)feat2, f2, n4);
    }

    // 4) Y2 = feat2 @ W0[0:256]  (fp32 out)
    gemm_mma<0><<<dim3(M2_ / 128, CH_ / 128), 256, GEMM_SMEM>>>(
        f2, C2_, w0t, 384, 256,
        nullptr, nullptr, nullptr, nullptr, nullptr,
        nullptr, nullptr, nullptr,
        y2, nullptr, CH_);

    // 5) x1 = BN(relu(feat1 @ W0[256:384] + gather(Y2) + b0)) -> fp16
    gemm_mma<2><<<dim3(M_ / 128, CH_ / 128), 256, GEMM_SMEM>>>(
        f1, C1_, w0t + 256, 384, 128,
        b0, gamma0, beta0, mean0, var0,
        y2, kidx, kw,
        nullptr, x1, CH_);

    // 6) out = BN(relu(x1 @ W1 + b1))
    gemm_mma<1><<<dim3(M_ / 128, CH_ / 128), 256, GEMM_SMEM>>>(
        x1, CH_, w1t, 256, 256,
        b1, gamma1, beta1, mean1, var1,
        nullptr, nullptr, nullptr,
        out, nullptr, CH_);
}